// round 1
// baseline (speedup 1.0000x reference)
#include <cuda_runtime.h>
#include <cuda_bf16.h>
#include <math.h>

// ---------------------------------------------------------------------------
// 2-layer GCN, N=1M nodes, E=4M edges, F: 4 -> 16 -> 2, log_softmax output.
//
// out1[d] = dinv[d] * ( sum_{e: dst=d} hs1[src_e] + hs1[d] ) + b1   (then relu)
// where hs1[i] = (x[i] @ W1) * dinv[i],  dinv[i] = rsqrt(1 + indeg[i])
// (self-loop folded into the +hs1[d] term; per-edge work needs no dinv loads)
// ---------------------------------------------------------------------------

#define NMAX 1048576  // N = 1,000,000 <= NMAX

__device__ int   g_deg [NMAX];
__device__ float g_dinv[NMAX];
__device__ float g_h1  [NMAX * 16];  // hs1 = (x@W1)*dinv
__device__ float g_a1  [NMAX * 16];  // edge accumulator layer 1
__device__ float g_h2  [NMAX * 2];   // hs2 = (h@W2)*dinv
__device__ float g_a2  [NMAX * 2];   // edge accumulator layer 2
__device__ int   g_ei64;             // 1 if edge_index is int64, 0 if int32

// --- dtype detection: int64 indices < 2^20 have all-zero high words --------
__global__ void k_detect(const unsigned* ei) {
    if (threadIdx.x == 0 && blockIdx.x == 0) {
        int nz = 0;
        for (int e = 0; e < 256; e++) nz += (ei[2 * e + 1] != 0u);
        g_ei64 = (nz == 0) ? 1 : 0;
    }
}

__device__ __forceinline__ void ld_edge(const void* ei, int E, int e, int& s, int& d) {
    if (g_ei64) {
        const long long* p = (const long long*)ei;
        s = (int)__ldg(p + e);
        d = (int)__ldg(p + E + e);
    } else {
        const int* p = (const int*)ei;
        s = __ldg(p + e);
        d = __ldg(p + E + e);
    }
}

// --- degree ---------------------------------------------------------------
__global__ void k_deg_init(int N) {
    int i = blockIdx.x * blockDim.x + threadIdx.x;
    if (i < N) g_deg[i] = 1;  // self loop
}

__global__ void k_deg(const void* ei, int E) {
    int e = blockIdx.x * blockDim.x + threadIdx.x;
    if (e >= E) return;
    int s, d;
    ld_edge(ei, E, e, s, d);
    atomicAdd(&g_deg[d], 1);
}

// --- layer 1 node pass: dinv, hs1 = (x@W1)*dinv, zero a1 ------------------
__global__ void k_l1(const float* __restrict__ x, const float* __restrict__ W1, int N) {
    int i = blockIdx.x * blockDim.x + threadIdx.x;
    if (i >= N) return;
    float4 xv = ((const float4*)x)[i];
    float di = rsqrtf((float)g_deg[i]);
    g_dinv[i] = di;

    float4* hp = (float4*)&g_h1[(long long)i * 16];
    float4* ap = (float4*)&g_a1[(long long)i * 16];
    const float4 z = make_float4(0.f, 0.f, 0.f, 0.f);
#pragma unroll
    for (int q = 0; q < 4; q++) {
        float4 h;
        float* hh = (float*)&h;
#pragma unroll
        for (int j = 0; j < 4; j++) {
            int k = q * 4 + j;
            hh[j] = (xv.x * __ldg(W1 + k) + xv.y * __ldg(W1 + 16 + k) +
                     xv.z * __ldg(W1 + 32 + k) + xv.w * __ldg(W1 + 48 + k)) * di;
        }
        hp[q] = h;
        ap[q] = z;
    }
}

// --- layer 1 edge scatter: a1[dst] += hs1[src] (4x red.v4.f32) ------------
__global__ void k_sc1(const void* ei, int E) {
    int e = blockIdx.x * blockDim.x + threadIdx.x;
    if (e >= E) return;
    int s, d;
    ld_edge(ei, E, e, s, d);
    const float4* hp = (const float4*)&g_h1[(long long)s * 16];
    float4* ap = (float4*)&g_a1[(long long)d * 16];
#pragma unroll
    for (int q = 0; q < 4; q++) {
        float4 v = __ldg(hp + q);
        asm volatile("red.global.add.v4.f32 [%0], {%1,%2,%3,%4};"
                     :: "l"(ap + q), "f"(v.x), "f"(v.y), "f"(v.z), "f"(v.w)
                     : "memory");
    }
}

// --- layer 2 node pass: h = relu(dinv*(a1+hs1)+b1); hs2=(h@W2)*dinv -------
__global__ void k_l2(const float* __restrict__ b1, const float* __restrict__ W2, int N) {
    int i = blockIdx.x * blockDim.x + threadIdx.x;
    if (i >= N) return;
    float di = g_dinv[i];
    const float4* hp = (const float4*)&g_h1[(long long)i * 16];
    const float4* ap = (const float4*)&g_a1[(long long)i * 16];
    float o0 = 0.f, o1 = 0.f;
#pragma unroll
    for (int q = 0; q < 4; q++) {
        float4 hv = hp[q];
        float4 av = ap[q];
        float* hh = (float*)&hv;
        float* aa = (float*)&av;
#pragma unroll
        for (int j = 0; j < 4; j++) {
            int k = q * 4 + j;
            float h = fmaxf(di * (aa[j] + hh[j]) + __ldg(b1 + k), 0.f);
            o0 += h * __ldg(W2 + 2 * k);
            o1 += h * __ldg(W2 + 2 * k + 1);
        }
    }
    ((float2*)g_h2)[i] = make_float2(o0 * di, o1 * di);
    ((float2*)g_a2)[i] = make_float2(0.f, 0.f);
}

// --- layer 2 edge scatter: a2[dst] += hs2[src] (red.v2.f32) ---------------
__global__ void k_sc2(const void* ei, int E) {
    int e = blockIdx.x * blockDim.x + threadIdx.x;
    if (e >= E) return;
    int s, d;
    ld_edge(ei, E, e, s, d);
    float2 v = __ldg(&((const float2*)g_h2)[s]);
    float2* ap = &((float2*)g_a2)[d];
    asm volatile("red.global.add.v2.f32 [%0], {%1,%2};"
                 :: "l"(ap), "f"(v.x), "f"(v.y)
                 : "memory");
}

// --- output: o = dinv*(a2+hs2)+b2; log_softmax over 2 classes -------------
__global__ void k_out(const float* __restrict__ b2, float* __restrict__ out, int N) {
    int i = blockIdx.x * blockDim.x + threadIdx.x;
    if (i >= N) return;
    float di = g_dinv[i];
    float2 a = ((const float2*)g_a2)[i];
    float2 h = ((const float2*)g_h2)[i];
    float o0 = di * (a.x + h.x) + __ldg(b2);
    float o1 = di * (a.y + h.y) + __ldg(b2 + 1);
    float m = fmaxf(o0, o1);
    float ls = m + logf(expf(o0 - m) + expf(o1 - m));
    ((float2*)out)[i] = make_float2(o0 - ls, o1 - ls);
}

extern "C" void kernel_launch(void* const* d_in, const int* in_sizes, int n_in,
                              void* d_out, int out_size) {
    const float* x  = (const float*)d_in[0];
    const void*  ei = d_in[1];
    // metadata order: x, edge_index, [num_nodes], W1, b1, W2, b2
    int wi = 2;
    if (n_in >= 7 && in_sizes[2] < 16) wi = 3;  // skip num_nodes scalar
    const float* W1 = (const float*)d_in[wi];
    const float* b1 = (const float*)d_in[wi + 1];
    const float* W2 = (const float*)d_in[wi + 2];
    const float* b2 = (const float*)d_in[wi + 3];

    int N = in_sizes[0] / 4;
    int E = in_sizes[1] / 2;

    const int T = 256;
    int gN = (N + T - 1) / T;
    int gE = (E + T - 1) / T;

    k_detect<<<1, 32>>>((const unsigned*)ei);
    k_deg_init<<<gN, T>>>(N);
    k_deg<<<gE, T>>>(ei, E);
    k_l1<<<gN, T>>>(x, W1, N);
    k_sc1<<<gE, T>>>(ei, E);
    k_l2<<<gN, T>>>(b1, W2, N);
    k_sc2<<<gE, T>>>(ei, E);
    k_out<<<gN, T>>>(b2, (float*)d_out, N);
}

// round 2
// speedup vs baseline: 1.9908x; 1.9908x over previous
#include <cuda_runtime.h>
#include <cuda_bf16.h>
#include <math.h>

// ---------------------------------------------------------------------------
// 2-layer GCN, N=1M, E=4M, 4 -> 16 -> 2, log_softmax.
//
// Linearity trick: layer-1 scatter moves xs = x*dinv (4 floats), W1 applied
// AFTER aggregation:  out1[d] = dinv[d]*((a1[d]+xs[d]) @ W1) + b1.
// Edge list converted once to packed int2 (+ fused degree count).
// ---------------------------------------------------------------------------

#define NMAX 1048576   // N = 1,000,000
#define EMAX 4194304   // E = 4,000,000

__device__ int2  g_edges[EMAX];      // packed (src, dst), int32
__device__ int   g_deg  [NMAX];
__device__ float g_dinv [NMAX];
__device__ float g_xs   [NMAX * 4];  // x * dinv          (16 MB, L2-resident)
__device__ float g_a1   [NMAX * 4];  // layer-1 edge acc  (16 MB, L2-resident)
__device__ float g_h2   [NMAX * 2];  // hs2 = (h@W2)*dinv ( 8 MB)
__device__ float g_a2   [NMAX * 2];  // layer-2 edge acc  ( 8 MB)
__device__ int   g_ei64;

// --- dtype detection: int64 indices < 2^20 have all-zero high words --------
__global__ void k_detect(const unsigned* ei) {
    if (threadIdx.x == 0 && blockIdx.x == 0) {
        int nz = 0;
        for (int e = 0; e < 256; e++) nz += (ei[2 * e + 1] != 0u);
        g_ei64 = (nz == 0) ? 1 : 0;
    }
}

__global__ void k_deg_init(int N) {
    int i = blockIdx.x * blockDim.x + threadIdx.x;
    if (i < N) g_deg[i] = 1;  // self loop
}

// --- convert edges to packed int2 + fused degree count --------------------
__global__ void k_conv(const void* ei, int E) {
    int e = blockIdx.x * blockDim.x + threadIdx.x;
    if (e >= E) return;
    int s, d;
    if (g_ei64) {
        const long long* p = (const long long*)ei;
        s = (int)__ldg(p + e);
        d = (int)__ldg(p + E + e);
    } else {
        const int* p = (const int*)ei;
        s = __ldg(p + e);
        d = __ldg(p + E + e);
    }
    g_edges[e] = make_int2(s, d);
    atomicAdd(&g_deg[d], 1);
}

// --- node pass 1: dinv, xs = x*dinv, zero a1 ------------------------------
__global__ void k_l1(const float* __restrict__ x, int N) {
    int i = blockIdx.x * blockDim.x + threadIdx.x;
    if (i >= N) return;
    float4 xv = ((const float4*)x)[i];
    float di = rsqrtf((float)g_deg[i]);
    g_dinv[i] = di;
    ((float4*)g_xs)[i] = make_float4(xv.x * di, xv.y * di, xv.z * di, xv.w * di);
    ((float4*)g_a1)[i] = make_float4(0.f, 0.f, 0.f, 0.f);
}

// --- layer-1 edge scatter: a1[dst] += xs[src]  (ONE red.v4 per edge) ------
__global__ void k_sc1(int E) {
    int e = blockIdx.x * blockDim.x + threadIdx.x;
    if (e >= E) return;
    int2 sd = g_edges[e];
    float4 v = __ldg(&((const float4*)g_xs)[sd.x]);
    float4* ap = &((float4*)g_a1)[sd.y];
    asm volatile("red.global.add.v4.f32 [%0], {%1,%2,%3,%4};"
                 :: "l"(ap), "f"(v.x), "f"(v.y), "f"(v.z), "f"(v.w)
                 : "memory");
}

// --- node pass 2: apply W1 post-aggregation, relu, W2, scale by dinv ------
__global__ void k_l2(const float* __restrict__ W1, const float* __restrict__ b1,
                     const float* __restrict__ W2, int N) {
    int i = blockIdx.x * blockDim.x + threadIdx.x;
    if (i >= N) return;
    float di = g_dinv[i];
    float4 xv = ((const float4*)g_xs)[i];
    float4 av = ((const float4*)g_a1)[i];
    float s0 = xv.x + av.x, s1 = xv.y + av.y, s2 = xv.z + av.z, s3 = xv.w + av.w;
    float o0 = 0.f, o1 = 0.f;
#pragma unroll
    for (int k = 0; k < 16; k++) {
        float h = di * (s0 * __ldg(W1 + k)      + s1 * __ldg(W1 + 16 + k) +
                        s2 * __ldg(W1 + 32 + k) + s3 * __ldg(W1 + 48 + k)) + __ldg(b1 + k);
        h = fmaxf(h, 0.f);
        o0 += h * __ldg(W2 + 2 * k);
        o1 += h * __ldg(W2 + 2 * k + 1);
    }
    ((float2*)g_h2)[i] = make_float2(o0 * di, o1 * di);
    ((float2*)g_a2)[i] = make_float2(0.f, 0.f);
}

// --- layer-2 edge scatter: a2[dst] += h2[src] -----------------------------
__global__ void k_sc2(int E) {
    int e = blockIdx.x * blockDim.x + threadIdx.x;
    if (e >= E) return;
    int2 sd = g_edges[e];
    float2 v = __ldg(&((const float2*)g_h2)[sd.x]);
    float2* ap = &((float2*)g_a2)[sd.y];
    asm volatile("red.global.add.v2.f32 [%0], {%1,%2};"
                 :: "l"(ap), "f"(v.x), "f"(v.y)
                 : "memory");
}

// --- output: o = dinv*(a2+h2)+b2; log_softmax over 2 classes --------------
__global__ void k_out(const float* __restrict__ b2, float* __restrict__ out, int N) {
    int i = blockIdx.x * blockDim.x + threadIdx.x;
    if (i >= N) return;
    float di = g_dinv[i];
    float2 a = ((const float2*)g_a2)[i];
    float2 h = ((const float2*)g_h2)[i];
    float o0 = di * (a.x + h.x) + __ldg(b2);
    float o1 = di * (a.y + h.y) + __ldg(b2 + 1);
    float m = fmaxf(o0, o1);
    float ls = m + logf(expf(o0 - m) + expf(o1 - m));
    ((float2*)out)[i] = make_float2(o0 - ls, o1 - ls);
}

extern "C" void kernel_launch(void* const* d_in, const int* in_sizes, int n_in,
                              void* d_out, int out_size) {
    const float* x  = (const float*)d_in[0];
    const void*  ei = d_in[1];
    int wi = 2;
    if (n_in >= 7 && in_sizes[2] < 16) wi = 3;  // skip num_nodes scalar
    const float* W1 = (const float*)d_in[wi];
    const float* b1 = (const float*)d_in[wi + 1];
    const float* W2 = (const float*)d_in[wi + 2];
    const float* b2 = (const float*)d_in[wi + 3];

    int N = in_sizes[0] / 4;
    int E = in_sizes[1] / 2;

    const int T = 256;
    int gN = (N + T - 1) / T;
    int gE = (E + T - 1) / T;

    k_detect<<<1, 32>>>((const unsigned*)ei);
    k_deg_init<<<gN, T>>>(N);
    k_conv<<<gE, T>>>(ei, E);
    k_l1<<<gN, T>>>(x, N);
    k_sc1<<<gE, T>>>(E);
    k_l2<<<gN, T>>>(W1, b1, W2, N);
    k_sc2<<<gE, T>>>(E);
    k_out<<<gN, T>>>(b2, (float*)d_out, N);
}